// round 2
// baseline (speedup 1.0000x reference)
#include <cuda_runtime.h>

#define IN_CH   64
#define OUT_CH  64
#define KS      3
#define GROUPS  8
#define FPG     8
#define H       256
#define WID     256
#define BATCH   8
#define TY      16
#define SM_W    260   // 258 padded cols + 2 pad -> multiple of 4 for aligned LDS.128

// scratch for per-sample dynamic kernels: [B][OUT_CH][3][3]
__device__ float g_ker[BATCH * OUT_CH * KS * KS];

// ker[b, oc*9+k] = leaky_relu( rep[b,:] . W[oc*9+k, :], 0.1 )
__global__ void weights_kernel(const float* __restrict__ rep,
                               const float* __restrict__ W) {
    __shared__ float rv[32];
    const int b = blockIdx.x;
    const int tid = threadIdx.x;
    if (tid < 32) rv[tid] = rep[b * 32 + tid];
    __syncthreads();
    if (tid < OUT_CH * KS * KS) {
        const float* wr = W + tid * 32;
        float acc = 0.f;
        #pragma unroll
        for (int i = 0; i < 32; ++i) acc += wr[i] * rv[i];
        g_ker[b * OUT_CH * KS * KS + tid] = acc > 0.f ? acc : 0.1f * acc;
    }
}

__global__ __launch_bounds__(256) void conv_kernel(const float* __restrict__ x,
                                                   float* __restrict__ out) {
    __shared__ float sm[(TY + 2) * SM_W];
    const int tileY = blockIdx.x;       // 0..15
    const int g     = blockIdx.y;       // 0..7
    const int b     = blockIdx.z;       // 0..7
    const int tid   = threadIdx.x;

    const float* xg = x + ((size_t)(b * IN_CH + g * FPG)) * (H * WID);

    // ---- load weights (72 floats) into registers (independent of smem) ----
    float w[72];
    {
        const float4* kp = (const float4*)(g_ker + (b * OUT_CH + g * FPG) * 9);
        #pragma unroll
        for (int i = 0; i < 18; ++i) {
            float4 v = kp[i];
            w[4*i+0] = v.x; w[4*i+1] = v.y; w[4*i+2] = v.z; w[4*i+3] = v.w;
        }
    }

    // ---- interior: sum 8 channels into shared, vectorized LDG.128 ----
    // items: 18 padded rows x 64 float4 groups = 1152
    #pragma unroll
    for (int i = 0; i < 5; ++i) {
        int item = tid + i * 256;
        if (item < (TY + 2) * 64) {
            int r  = item >> 6;
            int j4 = item & 63;
            int y = tileY * TY + r - 1;
            y = (y < 0) ? 1 : (y > H - 1 ? H - 2 : y);   // reflect pad=1
            const float4* p = (const float4*)(xg + (size_t)y * WID + 4 * j4);
            float sx = 0.f, sy = 0.f, sz = 0.f, sw = 0.f;
            #pragma unroll
            for (int c = 0; c < FPG; ++c) {
                float4 v = p[c * (H * WID / 4)];
                sx += v.x; sy += v.y; sz += v.z; sw += v.w;
            }
            float* d = sm + r * SM_W + 4 * j4 + 1;  // padded col = x+1
            d[0] = sx; d[1] = sy; d[2] = sz; d[3] = sw;
        }
    }
    // ---- halo columns: padded col 0 <- src x=1 ; padded col 257 <- src x=254 ----
    if (tid < 2 * (TY + 2)) {
        int r = tid >> 1, side = tid & 1;
        int y = tileY * TY + r - 1;
        y = (y < 0) ? 1 : (y > H - 1 ? H - 2 : y);
        int xs = side ? (WID - 2) : 1;
        float v = 0.f;
        #pragma unroll
        for (int c = 0; c < FPG; ++c) v += xg[(size_t)c * (H * WID) + (size_t)y * WID + xs];
        sm[r * SM_W + (side ? 257 : 0)] = v;
    }
    __syncthreads();

    // ---- compute: each thread does 1x4 output strips, 8 out channels ----
    const int q  = tid & 63;   // x-quad: outputs x = 4q .. 4q+3
    const int r0 = tid >> 6;   // 0..3
    float* ob = out + ((size_t)(b * OUT_CH + g * FPG)) * (H * WID) + 4 * q;

    #pragma unroll
    for (int rr0 = 0; rr0 < TY; rr0 += 4) {
        const int rr = rr0 + r0;
        // window: padded rows rr..rr+2, padded cols 4q..4q+5 (two aligned LDS.128 per row)
        float win[3][6];
        #pragma unroll
        for (int dy = 0; dy < 3; ++dy) {
            const float4* sp = (const float4*)(sm + (rr + dy) * SM_W + 4 * q);
            float4 a = sp[0], bb = sp[1];
            win[dy][0] = a.x;  win[dy][1] = a.y;  win[dy][2] = a.z;  win[dy][3] = a.w;
            win[dy][4] = bb.x; win[dy][5] = bb.y;
        }
        const int y = tileY * TY + rr;
        #pragma unroll
        for (int o = 0; o < 8; ++o) {
            float ax = 0.f, ay = 0.f, az = 0.f, aw = 0.f;
            #pragma unroll
            for (int dy = 0; dy < 3; ++dy) {
                #pragma unroll
                for (int dx = 0; dx < 3; ++dx) {
                    const float wv = w[o * 9 + dy * 3 + dx];
                    ax += wv * win[dy][dx + 0];
                    ay += wv * win[dy][dx + 1];
                    az += wv * win[dy][dx + 2];
                    aw += wv * win[dy][dx + 3];
                }
            }
            *(float4*)(ob + (size_t)o * (H * WID) + (size_t)y * WID) =
                make_float4(ax, ay, az, aw);
        }
    }
}

extern "C" void kernel_launch(void* const* d_in, const int* in_sizes, int n_in,
                              void* d_out, int out_size) {
    const float* x   = (const float*)d_in[0];
    const float* rep = (const float*)d_in[1];
    const float* W   = (const float*)d_in[2];
    float* out = (float*)d_out;

    weights_kernel<<<BATCH, OUT_CH * KS * KS>>>(rep, W);

    dim3 grid(H / TY, GROUPS, BATCH);
    conv_kernel<<<grid, 256>>>(x, out);
}

// round 3
// speedup vs baseline: 1.2579x; 1.2579x over previous
#include <cuda_runtime.h>

#define IN_CH   64
#define OUT_CH  64
#define KS      3
#define GROUPS  8
#define FPG     8
#define H       256
#define WID     256
#define BATCH   8
#define TY      16
#define SM_W    260   // 258 padded cols + 2 pad -> multiple of 4 for aligned LDS.128

__global__ __launch_bounds__(256) void fused_conv_kernel(const float* __restrict__ x,
                                                         const float* __restrict__ rep,
                                                         const float* __restrict__ W,
                                                         float* __restrict__ out) {
    __shared__ float sm[(TY + 2) * SM_W];
    __shared__ float wsm[FPG * 9];      // 72 dynamic weights for this (b, g)

    const int tileY = blockIdx.x;       // 0..15
    const int g     = blockIdx.y;       // 0..7
    const int b     = blockIdx.z;       // 0..7
    const int tid   = threadIdx.x;

    const float* xg = x + ((size_t)(b * IN_CH + g * FPG)) * (H * WID);

    // ---- weights: leaky_relu(rep[b] . W[row]) for rows g*72 .. g*72+71 ----
    if (tid < FPG * 9) {
        const float4* wr = (const float4*)(W + (size_t)(g * FPG * 9 + tid) * 32);
        const float4* rv = (const float4*)(rep + b * 32);
        float acc = 0.f;
        #pragma unroll
        for (int i = 0; i < 8; ++i) {
            float4 a = wr[i], r = rv[i];
            acc += a.x * r.x + a.y * r.y + a.z * r.z + a.w * r.w;
        }
        wsm[tid] = acc > 0.f ? acc : 0.1f * acc;
    }

    // ---- interior: sum 8 channels into shared, vectorized LDG.128 ----
    // items: 18 padded rows x 64 float4 groups = 1152
    #pragma unroll
    for (int i = 0; i < 5; ++i) {
        int item = tid + i * 256;
        if (item < (TY + 2) * 64) {
            int r  = item >> 6;
            int j4 = item & 63;
            int y = tileY * TY + r - 1;
            y = (y < 0) ? 1 : (y > H - 1 ? H - 2 : y);   // reflect pad=1
            const float4* p = (const float4*)(xg + (size_t)y * WID + 4 * j4);
            float sx = 0.f, sy = 0.f, sz = 0.f, sw = 0.f;
            #pragma unroll
            for (int c = 0; c < FPG; ++c) {
                float4 v = p[c * (H * WID / 4)];
                sx += v.x; sy += v.y; sz += v.z; sw += v.w;
            }
            float* d = sm + r * SM_W + 4 * j4 + 1;  // padded col = x+1
            d[0] = sx; d[1] = sy; d[2] = sz; d[3] = sw;
        }
    }
    // ---- halo columns: padded col 0 <- src x=1 ; padded col 257 <- src x=254 ----
    if (tid < 2 * (TY + 2)) {
        int r = tid >> 1, side = tid & 1;
        int y = tileY * TY + r - 1;
        y = (y < 0) ? 1 : (y > H - 1 ? H - 2 : y);
        int xs = side ? (WID - 2) : 1;
        float v = 0.f;
        #pragma unroll
        for (int c = 0; c < FPG; ++c) v += xg[(size_t)c * (H * WID) + (size_t)y * WID + xs];
        sm[r * SM_W + (side ? 257 : 0)] = v;
    }
    __syncthreads();

    // ---- compute: each thread does 1x4 output strips, 8 out channels ----
    const int q  = tid & 63;   // x-quad: outputs x = 4q .. 4q+3
    const int r0 = tid >> 6;   // 0..3
    float* ob = out + ((size_t)(b * OUT_CH + g * FPG)) * (H * WID) + 4 * q;

    #pragma unroll
    for (int rr0 = 0; rr0 < TY; rr0 += 4) {
        const int rr = rr0 + r0;
        // window: padded rows rr..rr+2, padded cols 4q..4q+5 (two aligned LDS.128 per row)
        float win[3][6];
        #pragma unroll
        for (int dy = 0; dy < 3; ++dy) {
            const float4* sp = (const float4*)(sm + (rr + dy) * SM_W + 4 * q);
            float4 a = sp[0], bb = sp[1];
            win[dy][0] = a.x;  win[dy][1] = a.y;  win[dy][2] = a.z;  win[dy][3] = a.w;
            win[dy][4] = bb.x; win[dy][5] = bb.y;
        }
        const int y = tileY * TY + rr;
        #pragma unroll
        for (int o = 0; o < 8; ++o) {
            float wo[9];
            #pragma unroll
            for (int j = 0; j < 9; ++j) wo[j] = wsm[o * 9 + j];
            float ax = 0.f, ay = 0.f, az = 0.f, aw = 0.f;
            #pragma unroll
            for (int dy = 0; dy < 3; ++dy) {
                #pragma unroll
                for (int dx = 0; dx < 3; ++dx) {
                    const float wv = wo[dy * 3 + dx];
                    ax += wv * win[dy][dx + 0];
                    ay += wv * win[dy][dx + 1];
                    az += wv * win[dy][dx + 2];
                    aw += wv * win[dy][dx + 3];
                }
            }
            *(float4*)(ob + (size_t)o * (H * WID) + (size_t)y * WID) =
                make_float4(ax, ay, az, aw);
        }
    }
}

extern "C" void kernel_launch(void* const* d_in, const int* in_sizes, int n_in,
                              void* d_out, int out_size) {
    const float* x   = (const float*)d_in[0];
    const float* rep = (const float*)d_in[1];
    const float* W   = (const float*)d_in[2];
    float* out = (float*)d_out;

    dim3 grid(H / TY, GROUPS, BATCH);
    fused_conv_kernel<<<grid, 256>>>(x, rep, W, out);
}